// round 1
// baseline (speedup 1.0000x reference)
#include <cuda_runtime.h>
#include <cuda_bf16.h>
#include <math.h>

// ---------------------------------------------------------------------------
// MambaFormerBlock: B=2, L=1024, D=1024, DIN=2048, DTR=64, DS=16, H=16, HD=64
// R = B*L = 2048 rows.
// ---------------------------------------------------------------------------

#define R_ROWS   2048
#define D_MODEL  1024
#define DIN      2048
#define DTR      64
#define DS       16
#define NHEAD    16
#define HDIM     64
#define LSEQ     1024
#define BATCH    2

// Scratch (device globals; no allocation allowed)
__device__ float g_xnm  [R_ROWS * D_MODEL];     // LN(x, mnorm)
__device__ float g_xna  [R_ROWS * D_MODEL];     // LN(x, norm1)
__device__ float g_xr   [R_ROWS * 2 * DIN];     // in_proj out: [u_raw | res]
__device__ float g_u    [R_ROWS * DIN];         // conv+silu
__device__ float g_dbc  [R_ROWS * 96];          // x_proj out: [dt(64)|B(16)|C(16)]
__device__ float g_delta[R_ROWS * DIN];         // softplus(dt @ dt_proj + b)
__device__ float g_y    [R_ROWS * DIN];         // scan out * silu(res)
__device__ float g_qkv  [R_ROWS * 1152];
__device__ float g_ao   [R_ROWS * D_MODEL];     // attention output (pre oattn)
__device__ float g_comb [R_ROWS * 2 * D_MODEL]; // [mamba_out | attn_out]
__device__ float g_fpre [R_ROWS * D_MODEL];     // fuse GEMM out (pre final LN)

// ---------------------------------------------------------------------------
// LayerNorm (optionally two (w,b) pairs sharing the same stats)
// ---------------------------------------------------------------------------
__global__ void __launch_bounds__(256) ln_dual_kernel(
    const float* __restrict__ x,
    const float* __restrict__ w1, const float* __restrict__ b1, float* __restrict__ o1,
    const float* __restrict__ w2, const float* __restrict__ b2, float* __restrict__ o2)
{
    const int Dm = D_MODEL;
    int row = blockIdx.x;
    const float* xp = x + (size_t)row * Dm;
    float s = 0.f, s2 = 0.f;
    for (int i = threadIdx.x; i < Dm; i += 256) { float v = xp[i]; s += v; s2 += v * v; }
    #pragma unroll
    for (int off = 16; off; off >>= 1) {
        s  += __shfl_xor_sync(0xffffffffu, s,  off);
        s2 += __shfl_xor_sync(0xffffffffu, s2, off);
    }
    __shared__ float rs[8], rs2[8];
    __shared__ float mean_s, inv_s;
    int w = threadIdx.x >> 5, l = threadIdx.x & 31;
    if (!l) { rs[w] = s; rs2[w] = s2; }
    __syncthreads();
    if (threadIdx.x == 0) {
        float a = 0.f, a2 = 0.f;
        #pragma unroll
        for (int i = 0; i < 8; i++) { a += rs[i]; a2 += rs2[i]; }
        float mean = a / Dm;
        float var  = a2 / Dm - mean * mean;
        mean_s = mean;
        inv_s  = rsqrtf(var + 1e-5f);
    }
    __syncthreads();
    float mean = mean_s, inv = inv_s;
    for (int i = threadIdx.x; i < Dm; i += 256) {
        float v = (xp[i] - mean) * inv;
        o1[(size_t)row * Dm + i] = v * w1[i] + b1[i];
        if (o2) o2[(size_t)row * Dm + i] = v * w2[i] + b2[i];
    }
}

// ---------------------------------------------------------------------------
// Tiled SGEMM: C[M,N] = A[M,K] @ W[N,K]^T (+bias) (+softplus) (+resid)
// BM=BN=64, BK=16, 256 threads, 4x4 per thread. M must be multiple of 64.
// ---------------------------------------------------------------------------
__global__ void __launch_bounds__(256) gemm_kernel(
    const float* __restrict__ A, int lda,
    const float* __restrict__ W, int K,
    const float* __restrict__ bias,
    const float* __restrict__ resid, int ldr,
    float* __restrict__ C, int ldc,
    int N, int act)
{
    __shared__ float As[16][68];
    __shared__ float Bs[16][68];
    int bm = blockIdx.y * 64, bn = blockIdx.x * 64;
    int tid = threadIdx.x;
    int tx = tid & 15, ty = tid >> 4;
    float acc[4][4] = {};
    for (int k0 = 0; k0 < K; k0 += 16) {
        #pragma unroll
        for (int j = 0; j < 4; j++) {
            int i  = tid + 256 * j;
            int mm = i >> 4, kk = i & 15;
            As[kk][mm] = A[(size_t)(bm + mm) * lda + k0 + kk];
            int gn = bn + mm;
            Bs[kk][mm] = (gn < N) ? W[(size_t)gn * K + k0 + kk] : 0.f;
        }
        __syncthreads();
        #pragma unroll
        for (int kk = 0; kk < 16; kk++) {
            float4 a4 = *(const float4*)&As[kk][ty * 4];
            float4 b4 = *(const float4*)&Bs[kk][tx * 4];
            float a[4] = { a4.x, a4.y, a4.z, a4.w };
            float b[4] = { b4.x, b4.y, b4.z, b4.w };
            #pragma unroll
            for (int i = 0; i < 4; i++)
                #pragma unroll
                for (int j = 0; j < 4; j++)
                    acc[i][j] += a[i] * b[j];
        }
        __syncthreads();
    }
    #pragma unroll
    for (int i = 0; i < 4; i++) {
        int gm = bm + ty * 4 + i;
        #pragma unroll
        for (int j = 0; j < 4; j++) {
            int gn = bn + tx * 4 + j;
            if (gn < N) {
                float v = acc[i][j];
                if (bias)  v += bias[gn];
                if (act)   v = (v > 20.f) ? v : log1pf(__expf(v));
                if (resid) v += resid[(size_t)gm * ldr + gn];
                C[(size_t)gm * ldc + gn] = v;
            }
        }
    }
}

// ---------------------------------------------------------------------------
// Depthwise causal conv (width 4) along L + bias + SiLU.
// input: g_xr[:, :DIN] (row stride 2*DIN), output g_u (row stride DIN)
// ---------------------------------------------------------------------------
__global__ void __launch_bounds__(256) conv_silu_kernel(
    const float* __restrict__ xr,
    const float* __restrict__ cw, const float* __restrict__ cb,
    float* __restrict__ u)
{
    int idx = blockIdx.x * 256 + threadIdx.x;       // over R_ROWS*DIN = 4M
    int d = idx & (DIN - 1);
    int r = idx >> 11;
    int l = r & (LSEQ - 1);
    float acc = cb[d];
    const float* base = xr + (size_t)r * (2 * DIN) + d;
    #pragma unroll
    for (int k = 0; k < 4; k++) {
        int l2 = l - 3 + k;
        if (l2 >= 0) acc += cw[d * 4 + k] * base[(size_t)(l2 - l) * (2 * DIN)];
    }
    float sv = acc / (1.f + __expf(-acc));
    u[idx] = sv;
}

// ---------------------------------------------------------------------------
// Selective scan. 16 lanes per (b,d) chain (lane = state n). A = -exp(A_log).
// Epilogue: y = (sum_n h*C + u*D_skip) * silu(res)
// ---------------------------------------------------------------------------
__global__ void __launch_bounds__(256) scan_kernel(
    const float* __restrict__ delta, const float* __restrict__ u,
    const float* __restrict__ dbc,   const float* __restrict__ xr,
    const float* __restrict__ A_log, const float* __restrict__ Dskip,
    float* __restrict__ y)
{
    int t = blockIdx.x * 256 + threadIdx.x;
    int chain = t >> 4;             // 0..4095
    int n = t & 15;
    int b = chain >> 11;            // /2048
    int d = chain & (DIN - 1);
    float An = -__expf(A_log[d * DS + n]);
    float Dv = Dskip[d];
    float h = 0.f;
    size_t rowbase = (size_t)b * LSEQ;
    for (int l = 0; l < LSEQ; l++) {
        size_t row = rowbase + l;
        float dv = delta[row * DIN + d];
        float uv = u[row * DIN + d];
        float Bn = dbc[row * 96 + DTR + n];
        float Cn = dbc[row * 96 + DTR + DS + n];
        h = __expf(dv * An) * h + dv * Bn * uv;
        float p = h * Cn;
        p += __shfl_xor_sync(0xffffffffu, p, 8, 16);
        p += __shfl_xor_sync(0xffffffffu, p, 4, 16);
        p += __shfl_xor_sync(0xffffffffu, p, 2, 16);
        p += __shfl_xor_sync(0xffffffffu, p, 1, 16);
        if (n == 0) {
            float res = xr[row * (2 * DIN) + DIN + d];
            float sres = res / (1.f + __expf(-res));
            y[row * DIN + d] = (p + uv * Dv) * sres;
        }
    }
}

// ---------------------------------------------------------------------------
// Causal MQA attention. Thread per query (q, o in regs), K/V tiles in smem,
// online softmax with rescale only when the running max changes.
// ---------------------------------------------------------------------------
__global__ void __launch_bounds__(128) attn_kernel(
    const float* __restrict__ qkv, float* __restrict__ out)
{
    __shared__ float ks[64 * 64];
    __shared__ float vs[64 * 64];
    int b = blockIdx.z, h = blockIdx.y;
    int ql = blockIdx.x * 128 + threadIdx.x;
    size_t qrow = ((size_t)b * LSEQ + ql) * 1152;
    float4 q4[16];
    #pragma unroll
    for (int i = 0; i < 16; i++) q4[i] = *(const float4*)(qkv + qrow + h * HDIM + i * 4);
    float4 o4[16];
    #pragma unroll
    for (int i = 0; i < 16; i++) o4[i] = make_float4(0.f, 0.f, 0.f, 0.f);
    float m = -1e30f, lsum = 0.f;
    int ntiles = blockIdx.x * 2 + 2;                 // keys through block's max query
    for (int tk = 0; tk < ntiles; tk++) {
        int s0 = tk * 64;
        __syncthreads();
        for (int i = threadIdx.x; i < 64 * 16; i += 128) {
            int s = i >> 4, jj = i & 15;
            const float* kr = qkv + ((size_t)b * LSEQ + s0 + s) * 1152;
            ((float4*)ks)[i] = *(const float4*)(kr + 1024 + jj * 4);
            ((float4*)vs)[i] = *(const float4*)(kr + 1088 + jj * 4);
        }
        __syncthreads();
        int kcount = ql - s0 + 1;
        if (kcount > 64) kcount = 64;
        for (int s = 0; s < kcount; s++) {
            const float4* kp = (const float4*)(ks + s * 64);
            float sc = 0.f;
            #pragma unroll
            for (int i = 0; i < 16; i++) {
                float4 kk = kp[i];
                sc += q4[i].x * kk.x; sc += q4[i].y * kk.y;
                sc += q4[i].z * kk.z; sc += q4[i].w * kk.w;
            }
            sc *= 0.125f;   // 1/sqrt(64)
            const float4* vp = (const float4*)(vs + s * 64);
            if (sc <= m) {
                float p = __expf(sc - m);
                lsum += p;
                #pragma unroll
                for (int i = 0; i < 16; i++) {
                    float4 vv = vp[i];
                    o4[i].x += p * vv.x; o4[i].y += p * vv.y;
                    o4[i].z += p * vv.z; o4[i].w += p * vv.w;
                }
            } else {
                float sc2 = __expf(m - sc);
                m = sc;
                lsum = lsum * sc2 + 1.f;
                #pragma unroll
                for (int i = 0; i < 16; i++) {
                    float4 vv = vp[i];
                    o4[i].x = o4[i].x * sc2 + vv.x; o4[i].y = o4[i].y * sc2 + vv.y;
                    o4[i].z = o4[i].z * sc2 + vv.z; o4[i].w = o4[i].w * sc2 + vv.w;
                }
            }
        }
    }
    float inv = 1.f / lsum;
    float* op = out + ((size_t)b * LSEQ + ql) * D_MODEL + h * HDIM;
    #pragma unroll
    for (int i = 0; i < 16; i++) {
        float4 vv;
        vv.x = o4[i].x * inv; vv.y = o4[i].y * inv;
        vv.z = o4[i].z * inv; vv.w = o4[i].w * inv;
        *(float4*)(op + i * 4) = vv;
    }
}

// ---------------------------------------------------------------------------
// Launch
// ---------------------------------------------------------------------------
extern "C" void kernel_launch(void* const* d_in, const int* in_sizes, int n_in,
                              void* d_out, int out_size)
{
    const float* x          = (const float*)d_in[0];
    const float* mnorm_w    = (const float*)d_in[1];
    const float* mnorm_b    = (const float*)d_in[2];
    const float* in_proj_w  = (const float*)d_in[3];
    const float* conv_w     = (const float*)d_in[4];
    const float* conv_b     = (const float*)d_in[5];
    const float* x_proj_w   = (const float*)d_in[6];
    const float* dt_proj_w  = (const float*)d_in[7];
    const float* dt_proj_b  = (const float*)d_in[8];
    const float* A_log      = (const float*)d_in[9];
    const float* D_skip     = (const float*)d_in[10];
    const float* out_proj_w = (const float*)d_in[11];
    const float* norm1_w    = (const float*)d_in[12];
    const float* norm1_b    = (const float*)d_in[13];
    const float* wqkv_w     = (const float*)d_in[14];
    const float* wqkv_b     = (const float*)d_in[15];
    const float* oattn_w    = (const float*)d_in[16];
    const float* oattn_b    = (const float*)d_in[17];
    const float* fuse_w     = (const float*)d_in[18];
    const float* fuse_b     = (const float*)d_in[19];
    const float* fln_w      = (const float*)d_in[20];
    const float* fln_b      = (const float*)d_in[21];
    float* out = (float*)d_out;

    float *xnm, *xna, *xr, *u, *dbc, *delta, *y, *qkv, *ao, *comb, *fpre;
    cudaGetSymbolAddress((void**)&xnm,   g_xnm);
    cudaGetSymbolAddress((void**)&xna,   g_xna);
    cudaGetSymbolAddress((void**)&xr,    g_xr);
    cudaGetSymbolAddress((void**)&u,     g_u);
    cudaGetSymbolAddress((void**)&dbc,   g_dbc);
    cudaGetSymbolAddress((void**)&delta, g_delta);
    cudaGetSymbolAddress((void**)&y,     g_y);
    cudaGetSymbolAddress((void**)&qkv,   g_qkv);
    cudaGetSymbolAddress((void**)&ao,    g_ao);
    cudaGetSymbolAddress((void**)&comb,  g_comb);
    cudaGetSymbolAddress((void**)&fpre,  g_fpre);

    // 1. Both input LayerNorms (shared stats)
    ln_dual_kernel<<<R_ROWS, 256>>>(x, mnorm_w, mnorm_b, xnm, norm1_w, norm1_b, xna);

    // 2. in_proj: xr = xnm @ in_proj_w^T   (2048 x 4096, K=1024)
    gemm_kernel<<<dim3(4096 / 64, R_ROWS / 64), 256>>>(
        xnm, D_MODEL, in_proj_w, D_MODEL, nullptr, nullptr, 0, xr, 2 * DIN, 2 * DIN, 0);

    // 3. depthwise conv + SiLU -> u
    conv_silu_kernel<<<(R_ROWS * DIN) / 256, 256>>>(xr, conv_w, conv_b, u);

    // 4. x_proj: dbc = u @ x_proj_w^T   (2048 x 96, K=2048)
    gemm_kernel<<<dim3(2, R_ROWS / 64), 256>>>(
        u, DIN, x_proj_w, DIN, nullptr, nullptr, 0, dbc, 96, 96, 0);

    // 5. dt_proj + softplus: delta (2048 x 2048, K=64, lda=96)
    gemm_kernel<<<dim3(DIN / 64, R_ROWS / 64), 256>>>(
        dbc, 96, dt_proj_w, DTR, dt_proj_b, nullptr, 0, delta, DIN, DIN, 1);

    // 6. selective scan (+ D_skip + silu(res) gate)
    scan_kernel<<<(BATCH * DIN * 16) / 256, 256>>>(delta, u, dbc, xr, A_log, D_skip, y);

    // 7. out_proj + residual x -> comb[:, :1024]
    gemm_kernel<<<dim3(D_MODEL / 64, R_ROWS / 64), 256>>>(
        y, DIN, out_proj_w, DIN, nullptr, x, D_MODEL, comb, 2 * D_MODEL, D_MODEL, 0);

    // 8. wqkv (+bias): qkv (2048 x 1152, K=1024)
    gemm_kernel<<<dim3(1152 / 64, R_ROWS / 64), 256>>>(
        xna, D_MODEL, wqkv_w, D_MODEL, wqkv_b, nullptr, 0, qkv, 1152, 1152, 0);

    // 9. causal MQA attention -> ao
    attn_kernel<<<dim3(LSEQ / 128, NHEAD, BATCH), 128>>>(qkv, ao);

    // 10. oattn (+bias) + residual x -> comb[:, 1024:]
    gemm_kernel<<<dim3(D_MODEL / 64, R_ROWS / 64), 256>>>(
        ao, D_MODEL, oattn_w, D_MODEL, oattn_b, x, D_MODEL, comb + D_MODEL, 2 * D_MODEL, D_MODEL, 0);

    // 11. fuse GEMM (+bias): fpre = comb @ fuse_w^T  (2048 x 1024, K=2048)
    gemm_kernel<<<dim3(D_MODEL / 64, R_ROWS / 64), 256>>>(
        comb, 2 * D_MODEL, fuse_w, 2 * D_MODEL, fuse_b, nullptr, 0, fpre, D_MODEL, D_MODEL, 0);

    // 12. final LayerNorm -> out
    ln_dual_kernel<<<R_ROWS, 256>>>(fpre, fln_w, fln_b, out, nullptr, nullptr, nullptr);
}

// round 2
// speedup vs baseline: 1.4366x; 1.4366x over previous
#include <cuda_runtime.h>
#include <cuda_bf16.h>
#include <math.h>

// ---------------------------------------------------------------------------
// MambaFormerBlock: B=2, L=1024, D=1024, DIN=2048, DTR=64, DS=16, H=16, HD=64
// R = B*L = 2048 rows. TF32 tensor-core GEMMs (mma.sync.m16n8k8).
// ---------------------------------------------------------------------------

#define R_ROWS   2048
#define D_MODEL  1024
#define DIN      2048
#define DTR      64
#define DS       16
#define NHEAD    16
#define HDIM     64
#define LSEQ     1024
#define BATCH    2
#define XP_SPLIT 8

// Scratch (device globals; no allocation allowed)
__device__ float g_xnm  [R_ROWS * D_MODEL];
__device__ float g_xna  [R_ROWS * D_MODEL];
__device__ float g_xr   [R_ROWS * 2 * DIN];
__device__ float g_u    [R_ROWS * DIN];
__device__ float g_dbc  [R_ROWS * 96];
__device__ float g_xpart[XP_SPLIT * R_ROWS * 96];
__device__ float g_delta[R_ROWS * DIN];
__device__ float g_y    [R_ROWS * DIN];
__device__ float g_qkv  [R_ROWS * 1152];
__device__ float g_ao   [R_ROWS * D_MODEL];
__device__ float g_comb [R_ROWS * 2 * D_MODEL];
__device__ float g_fpre [R_ROWS * D_MODEL];

// ---------------------------------------------------------------------------
// LayerNorm (optionally two (w,b) pairs sharing the same stats)
// ---------------------------------------------------------------------------
__global__ void __launch_bounds__(256) ln_dual_kernel(
    const float* __restrict__ x,
    const float* __restrict__ w1, const float* __restrict__ b1, float* __restrict__ o1,
    const float* __restrict__ w2, const float* __restrict__ b2, float* __restrict__ o2)
{
    const int Dm = D_MODEL;
    int row = blockIdx.x;
    const float* xp = x + (size_t)row * Dm;
    float s = 0.f, s2 = 0.f;
    for (int i = threadIdx.x; i < Dm; i += 256) { float v = xp[i]; s += v; s2 += v * v; }
    #pragma unroll
    for (int off = 16; off; off >>= 1) {
        s  += __shfl_xor_sync(0xffffffffu, s,  off);
        s2 += __shfl_xor_sync(0xffffffffu, s2, off);
    }
    __shared__ float rs[8], rs2[8];
    __shared__ float mean_s, inv_s;
    int w = threadIdx.x >> 5, l = threadIdx.x & 31;
    if (!l) { rs[w] = s; rs2[w] = s2; }
    __syncthreads();
    if (threadIdx.x == 0) {
        float a = 0.f, a2 = 0.f;
        #pragma unroll
        for (int i = 0; i < 8; i++) { a += rs[i]; a2 += rs2[i]; }
        float mean = a / Dm;
        float var  = a2 / Dm - mean * mean;
        mean_s = mean;
        inv_s  = rsqrtf(var + 1e-5f);
    }
    __syncthreads();
    float mean = mean_s, inv = inv_s;
    for (int i = threadIdx.x; i < Dm; i += 256) {
        float v = (xp[i] - mean) * inv;
        o1[(size_t)row * Dm + i] = v * w1[i] + b1[i];
        if (o2) o2[(size_t)row * Dm + i] = v * w2[i] + b2[i];
    }
}

// ---------------------------------------------------------------------------
// TF32 tensor-core GEMM: C[M,N] = A[M,K] @ W[N,K]^T (+bias)(+softplus)(+resid)
// BM=128, BN=128, BK=32. 256 threads = 8 warps; warp tile 64x32 via m16n8k8.
// blockIdx.x = n-tile, blockIdx.y = m-tile, blockIdx.z = split-K slice.
// ---------------------------------------------------------------------------
__device__ __forceinline__ unsigned f2tf(float x) {
    unsigned u;
    asm("cvt.rna.tf32.f32 %0, %1;" : "=r"(u) : "f"(x));
    return u;
}

__device__ __forceinline__ void mma_tf32(float* d, const unsigned* a, const unsigned* b) {
    asm volatile(
        "mma.sync.aligned.m16n8k8.row.col.f32.tf32.tf32.f32 "
        "{%0,%1,%2,%3}, {%4,%5,%6,%7}, {%8,%9}, {%0,%1,%2,%3};"
        : "+f"(d[0]), "+f"(d[1]), "+f"(d[2]), "+f"(d[3])
        : "r"(a[0]), "r"(a[1]), "r"(a[2]), "r"(a[3]), "r"(b[0]), "r"(b[1]));
}

#define BKP 36   // padded row length (floats) for BK=32

__global__ void __launch_bounds__(256) gemm_tf32_kernel(
    const float* __restrict__ A, int lda,
    const float* __restrict__ W, int ldw,
    int klen,                       // K length handled by this z-slice
    const float* __restrict__ bias,
    const float* __restrict__ resid, int ldr,
    float* __restrict__ C, int ldc,
    int N, int act)
{
    __shared__ unsigned As[128][BKP];
    __shared__ unsigned Bs[128][BKP];

    const int tid  = threadIdx.x;
    const int lane = tid & 31;
    const int wid  = tid >> 5;
    const int wm   = wid & 1;          // 0..1  -> warp m origin
    const int wn   = wid >> 1;         // 0..3  -> warp n origin
    const int m0   = wm * 64;
    const int n0   = wn * 32;
    const int qr   = lane >> 2;        // 0..7
    const int qc   = lane & 3;         // 0..3

    const int bm = blockIdx.y * 128;
    const int bn = blockIdx.x * 128;
    const int ks = blockIdx.z * klen;  // split-K start

    float acc[4][4][4];
    #pragma unroll
    for (int i = 0; i < 4; i++)
        #pragma unroll
        for (int j = 0; j < 4; j++)
            #pragma unroll
            for (int r = 0; r < 4; r++) acc[i][j][r] = 0.f;

    for (int k0 = 0; k0 < klen; k0 += 32) {
        // load A tile: 128 x 32 floats = 1024 float4, 4 per thread
        #pragma unroll
        for (int i = 0; i < 4; i++) {
            int idx = tid + i * 256;
            int row = idx >> 3;
            int ch  = idx & 7;
            float4 v = *(const float4*)&A[(size_t)(bm + row) * lda + ks + k0 + ch * 4];
            unsigned* dst = &As[row][ch * 4];
            dst[0] = f2tf(v.x); dst[1] = f2tf(v.y); dst[2] = f2tf(v.z); dst[3] = f2tf(v.w);
        }
        // load W tile (rows = output cols), guard against N edge
        #pragma unroll
        for (int i = 0; i < 4; i++) {
            int idx = tid + i * 256;
            int row = idx >> 3;
            int ch  = idx & 7;
            float4 v = make_float4(0.f, 0.f, 0.f, 0.f);
            if (bn + row < N)
                v = *(const float4*)&W[(size_t)(bn + row) * ldw + ks + k0 + ch * 4];
            unsigned* dst = &Bs[row][ch * 4];
            dst[0] = f2tf(v.x); dst[1] = f2tf(v.y); dst[2] = f2tf(v.z); dst[3] = f2tf(v.w);
        }
        __syncthreads();

        #pragma unroll
        for (int kc = 0; kc < 32; kc += 8) {
            unsigned af[4][4], bf[4][2];
            #pragma unroll
            for (int mt = 0; mt < 4; mt++) {
                int r0 = m0 + mt * 16 + qr;
                af[mt][0] = As[r0][kc + qc];
                af[mt][1] = As[r0 + 8][kc + qc];
                af[mt][2] = As[r0][kc + qc + 4];
                af[mt][3] = As[r0 + 8][kc + qc + 4];
            }
            #pragma unroll
            for (int nt = 0; nt < 4; nt++) {
                int c0 = n0 + nt * 8 + qr;
                bf[nt][0] = Bs[c0][kc + qc];
                bf[nt][1] = Bs[c0][kc + qc + 4];
            }
            #pragma unroll
            for (int mt = 0; mt < 4; mt++)
                #pragma unroll
                for (int nt = 0; nt < 4; nt++)
                    mma_tf32(acc[mt][nt], af[mt], bf[nt]);
        }
        __syncthreads();
    }

    // epilogue
    #pragma unroll
    for (int mt = 0; mt < 4; mt++) {
        #pragma unroll
        for (int nt = 0; nt < 4; nt++) {
            int r = bm + m0 + mt * 16 + qr;
            int c = bn + n0 + nt * 8 + 2 * qc;
            #pragma unroll
            for (int half = 0; half < 2; half++) {
                int rr = r + half * 8;
                #pragma unroll
                for (int cc = 0; cc < 2; cc++) {
                    int gc = c + cc;
                    if (gc < N) {
                        float v = acc[mt][nt][half * 2 + cc];
                        if (bias)  v += bias[gc];
                        if (act)   v = (v > 20.f) ? v : log1pf(__expf(v));
                        if (resid) v += resid[(size_t)rr * ldr + gc];
                        C[(size_t)rr * ldc + gc] = v;
                    }
                }
            }
        }
    }
}

// reduce split-K partials for x_proj: dbc = sum_z xpart[z]
__global__ void __launch_bounds__(256) reduce_xp_kernel(
    const float* __restrict__ part, float* __restrict__ out)
{
    int i = blockIdx.x * 256 + threadIdx.x;
    const int total = R_ROWS * 96;
    if (i < total) {
        float s = 0.f;
        #pragma unroll
        for (int z = 0; z < XP_SPLIT; z++) s += part[(size_t)z * total + i];
        out[i] = s;
    }
}

// ---------------------------------------------------------------------------
// Depthwise causal conv (width 4) along L + bias + SiLU.
// ---------------------------------------------------------------------------
__global__ void __launch_bounds__(256) conv_silu_kernel(
    const float* __restrict__ xr,
    const float* __restrict__ cw, const float* __restrict__ cb,
    float* __restrict__ u)
{
    int idx = blockIdx.x * 256 + threadIdx.x;
    int d = idx & (DIN - 1);
    int r = idx >> 11;
    int l = r & (LSEQ - 1);
    float acc = cb[d];
    const float* base = xr + (size_t)r * (2 * DIN) + d;
    #pragma unroll
    for (int k = 0; k < 4; k++) {
        int l2 = l - 3 + k;
        if (l2 >= 0) acc += cw[d * 4 + k] * base[(size_t)(l2 - l) * (2 * DIN)];
    }
    float sv = acc / (1.f + __expf(-acc));
    u[idx] = sv;
}

// ---------------------------------------------------------------------------
// Selective scan. 16 lanes per (b,d) chain (lane = state n).
// ---------------------------------------------------------------------------
__global__ void __launch_bounds__(256) scan_kernel(
    const float* __restrict__ delta, const float* __restrict__ u,
    const float* __restrict__ dbc,   const float* __restrict__ xr,
    const float* __restrict__ A_log, const float* __restrict__ Dskip,
    float* __restrict__ y)
{
    int t = blockIdx.x * 256 + threadIdx.x;
    int chain = t >> 4;
    int n = t & 15;
    int b = chain >> 11;
    int d = chain & (DIN - 1);
    float An = -__expf(A_log[d * DS + n]);
    float Dv = Dskip[d];
    float h = 0.f;
    size_t rowbase = (size_t)b * LSEQ;
    for (int l = 0; l < LSEQ; l++) {
        size_t row = rowbase + l;
        float dv = delta[row * DIN + d];
        float uv = u[row * DIN + d];
        float Bn = dbc[row * 96 + DTR + n];
        float Cn = dbc[row * 96 + DTR + DS + n];
        h = __expf(dv * An) * h + dv * Bn * uv;
        float p = h * Cn;
        p += __shfl_xor_sync(0xffffffffu, p, 8, 16);
        p += __shfl_xor_sync(0xffffffffu, p, 4, 16);
        p += __shfl_xor_sync(0xffffffffu, p, 2, 16);
        p += __shfl_xor_sync(0xffffffffu, p, 1, 16);
        if (n == 0) {
            float res = xr[row * (2 * DIN) + DIN + d];
            float sres = res / (1.f + __expf(-res));
            y[row * DIN + d] = (p + uv * Dv) * sres;
        }
    }
}

// ---------------------------------------------------------------------------
// Causal MQA attention. Thread per query, K/V tiles in smem, online softmax.
// ---------------------------------------------------------------------------
__global__ void __launch_bounds__(128) attn_kernel(
    const float* __restrict__ qkv, float* __restrict__ out)
{
    __shared__ float ks[64 * 64];
    __shared__ float vs[64 * 64];
    int b = blockIdx.z, h = blockIdx.y;
    int ql = blockIdx.x * 128 + threadIdx.x;
    size_t qrow = ((size_t)b * LSEQ + ql) * 1152;
    float4 q4[16];
    #pragma unroll
    for (int i = 0; i < 16; i++) q4[i] = *(const float4*)(qkv + qrow + h * HDIM + i * 4);
    float4 o4[16];
    #pragma unroll
    for (int i = 0; i < 16; i++) o4[i] = make_float4(0.f, 0.f, 0.f, 0.f);
    float m = -1e30f, lsum = 0.f;
    int ntiles = blockIdx.x * 2 + 2;
    for (int tk = 0; tk < ntiles; tk++) {
        int s0 = tk * 64;
        __syncthreads();
        for (int i = threadIdx.x; i < 64 * 16; i += 128) {
            int s = i >> 4, jj = i & 15;
            const float* kr = qkv + ((size_t)b * LSEQ + s0 + s) * 1152;
            ((float4*)ks)[i] = *(const float4*)(kr + 1024 + jj * 4);
            ((float4*)vs)[i] = *(const float4*)(kr + 1088 + jj * 4);
        }
        __syncthreads();
        int kcount = ql - s0 + 1;
        if (kcount > 64) kcount = 64;
        for (int s = 0; s < kcount; s++) {
            const float4* kp = (const float4*)(ks + s * 64);
            float sc = 0.f;
            #pragma unroll
            for (int i = 0; i < 16; i++) {
                float4 kk = kp[i];
                sc += q4[i].x * kk.x; sc += q4[i].y * kk.y;
                sc += q4[i].z * kk.z; sc += q4[i].w * kk.w;
            }
            sc *= 0.125f;
            const float4* vp = (const float4*)(vs + s * 64);
            if (sc <= m) {
                float p = __expf(sc - m);
                lsum += p;
                #pragma unroll
                for (int i = 0; i < 16; i++) {
                    float4 vv = vp[i];
                    o4[i].x += p * vv.x; o4[i].y += p * vv.y;
                    o4[i].z += p * vv.z; o4[i].w += p * vv.w;
                }
            } else {
                float sc2 = __expf(m - sc);
                m = sc;
                lsum = lsum * sc2 + 1.f;
                #pragma unroll
                for (int i = 0; i < 16; i++) {
                    float4 vv = vp[i];
                    o4[i].x = o4[i].x * sc2 + vv.x; o4[i].y = o4[i].y * sc2 + vv.y;
                    o4[i].z = o4[i].z * sc2 + vv.z; o4[i].w = o4[i].w * sc2 + vv.w;
                }
            }
        }
    }
    float inv = 1.f / lsum;
    float* op = out + ((size_t)b * LSEQ + ql) * D_MODEL + h * HDIM;
    #pragma unroll
    for (int i = 0; i < 16; i++) {
        float4 vv;
        vv.x = o4[i].x * inv; vv.y = o4[i].y * inv;
        vv.z = o4[i].z * inv; vv.w = o4[i].w * inv;
        *(float4*)(op + i * 4) = vv;
    }
}

// ---------------------------------------------------------------------------
// Launch
// ---------------------------------------------------------------------------
extern "C" void kernel_launch(void* const* d_in, const int* in_sizes, int n_in,
                              void* d_out, int out_size)
{
    const float* x          = (const float*)d_in[0];
    const float* mnorm_w    = (const float*)d_in[1];
    const float* mnorm_b    = (const float*)d_in[2];
    const float* in_proj_w  = (const float*)d_in[3];
    const float* conv_w     = (const float*)d_in[4];
    const float* conv_b     = (const float*)d_in[5];
    const float* x_proj_w   = (const float*)d_in[6];
    const float* dt_proj_w  = (const float*)d_in[7];
    const float* dt_proj_b  = (const float*)d_in[8];
    const float* A_log      = (const float*)d_in[9];
    const float* D_skip     = (const float*)d_in[10];
    const float* out_proj_w = (const float*)d_in[11];
    const float* norm1_w    = (const float*)d_in[12];
    const float* norm1_b    = (const float*)d_in[13];
    const float* wqkv_w     = (const float*)d_in[14];
    const float* wqkv_b     = (const float*)d_in[15];
    const float* oattn_w    = (const float*)d_in[16];
    const float* oattn_b    = (const float*)d_in[17];
    const float* fuse_w     = (const float*)d_in[18];
    const float* fuse_b     = (const float*)d_in[19];
    const float* fln_w      = (const float*)d_in[20];
    const float* fln_b      = (const float*)d_in[21];
    float* out = (float*)d_out;

    float *xnm, *xna, *xr, *u, *dbc, *xpart, *delta, *y, *qkv, *ao, *comb, *fpre;
    cudaGetSymbolAddress((void**)&xnm,   g_xnm);
    cudaGetSymbolAddress((void**)&xna,   g_xna);
    cudaGetSymbolAddress((void**)&xr,    g_xr);
    cudaGetSymbolAddress((void**)&u,     g_u);
    cudaGetSymbolAddress((void**)&dbc,   g_dbc);
    cudaGetSymbolAddress((void**)&xpart, g_xpart);
    cudaGetSymbolAddress((void**)&delta, g_delta);
    cudaGetSymbolAddress((void**)&y,     g_y);
    cudaGetSymbolAddress((void**)&qkv,   g_qkv);
    cudaGetSymbolAddress((void**)&ao,    g_ao);
    cudaGetSymbolAddress((void**)&comb,  g_comb);
    cudaGetSymbolAddress((void**)&fpre,  g_fpre);

    // 1. Both input LayerNorms (shared stats)
    ln_dual_kernel<<<R_ROWS, 256>>>(x, mnorm_w, mnorm_b, xnm, norm1_w, norm1_b, xna);

    // 2. in_proj: xr = xnm @ in_proj_w^T   (2048 x 4096, K=1024)
    gemm_tf32_kernel<<<dim3(4096 / 128, R_ROWS / 128, 1), 256>>>(
        xnm, D_MODEL, in_proj_w, D_MODEL, D_MODEL,
        nullptr, nullptr, 0, xr, 2 * DIN, 2 * DIN, 0);

    // 3. depthwise conv + SiLU -> u
    conv_silu_kernel<<<(R_ROWS * DIN) / 256, 256>>>(xr, conv_w, conv_b, u);

    // 4. x_proj split-K: partials (2048 x 96, K=2048, 8 slices of 256)
    gemm_tf32_kernel<<<dim3(1, R_ROWS / 128, XP_SPLIT), 256>>>(
        u, DIN, x_proj_w, DIN, DIN / XP_SPLIT,
        nullptr, nullptr, 0, xpart, 96, 96, 0);
    reduce_xp_kernel<<<(R_ROWS * 96 + 255) / 256, 256>>>(xpart, dbc);

    // 5. dt_proj + softplus: delta (2048 x 2048, K=64, lda=96)
    gemm_tf32_kernel<<<dim3(DIN / 128, R_ROWS / 128, 1), 256>>>(
        dbc, 96, dt_proj_w, DTR, DTR,
        dt_proj_b, nullptr, 0, delta, DIN, DIN, 1);

    // 6. selective scan (+ D_skip + silu(res) gate)
    scan_kernel<<<(BATCH * DIN * 16) / 256, 256>>>(delta, u, dbc, xr, A_log, D_skip, y);

    // 7. out_proj + residual x -> comb[:, :1024]
    gemm_tf32_kernel<<<dim3(D_MODEL / 128, R_ROWS / 128, 1), 256>>>(
        y, DIN, out_proj_w, DIN, DIN,
        nullptr, x, D_MODEL, comb, 2 * D_MODEL, D_MODEL, 0);

    // 8. wqkv (+bias): qkv (2048 x 1152, K=1024)
    gemm_tf32_kernel<<<dim3(1152 / 128, R_ROWS / 128, 1), 256>>>(
        xna, D_MODEL, wqkv_w, D_MODEL, D_MODEL,
        wqkv_b, nullptr, 0, qkv, 1152, 1152, 0);

    // 9. causal MQA attention -> ao
    attn_kernel<<<dim3(LSEQ / 128, NHEAD, BATCH), 128>>>(qkv, ao);

    // 10. oattn (+bias) + residual x -> comb[:, 1024:]
    gemm_tf32_kernel<<<dim3(D_MODEL / 128, R_ROWS / 128, 1), 256>>>(
        ao, D_MODEL, oattn_w, D_MODEL, D_MODEL,
        oattn_b, x, D_MODEL, comb + D_MODEL, 2 * D_MODEL, D_MODEL, 0);

    // 11. fuse GEMM (+bias): fpre = comb @ fuse_w^T  (2048 x 1024, K=2048)
    gemm_tf32_kernel<<<dim3(D_MODEL / 128, R_ROWS / 128, 1), 256>>>(
        comb, 2 * D_MODEL, fuse_w, 2 * D_MODEL, 2 * D_MODEL,
        fuse_b, nullptr, 0, fpre, D_MODEL, D_MODEL, 0);

    // 12. final LayerNorm -> out
    ln_dual_kernel<<<R_ROWS, 256>>>(fpre, fln_w, fln_b, out, nullptr, nullptr, nullptr);
}

// round 3
// speedup vs baseline: 1.5034x; 1.0465x over previous
#include <cuda_runtime.h>
#include <cuda_bf16.h>
#include <math.h>

// ---------------------------------------------------------------------------
// MambaFormerBlock: B=2, L=1024, D=1024, DIN=2048, DTR=64, DS=16, H=16, HD=64
// R = B*L = 2048 rows. TF32 tensor-core GEMMs, double-buffered.
// ---------------------------------------------------------------------------

#define R_ROWS   2048
#define D_MODEL  1024
#define DIN      2048
#define DTR      64
#define DS       16
#define NHEAD    16
#define HDIM     64
#define LSEQ     1024
#define BATCH    2
#define XP_SPLIT 8

// Scratch (device globals; no allocation allowed)
__device__ float g_xnm  [R_ROWS * D_MODEL];
__device__ float g_xna  [R_ROWS * D_MODEL];
__device__ float g_xr   [R_ROWS * 2 * DIN];
__device__ float g_u    [R_ROWS * DIN];
__device__ float g_dbc  [R_ROWS * 96];
__device__ float g_xpart[XP_SPLIT * R_ROWS * 96];
__device__ float g_delta[R_ROWS * DIN];
__device__ float g_y    [R_ROWS * DIN];
__device__ float g_qkv  [R_ROWS * 1152];
__device__ float g_ao   [R_ROWS * D_MODEL];
__device__ float g_comb [R_ROWS * 2 * D_MODEL];
__device__ float g_fpre [R_ROWS * D_MODEL];

// ---------------------------------------------------------------------------
// LayerNorm (optionally two (w,b) pairs sharing the same stats)
// ---------------------------------------------------------------------------
__global__ void __launch_bounds__(256) ln_dual_kernel(
    const float* __restrict__ x,
    const float* __restrict__ w1, const float* __restrict__ b1, float* __restrict__ o1,
    const float* __restrict__ w2, const float* __restrict__ b2, float* __restrict__ o2)
{
    const int Dm = D_MODEL;
    int row = blockIdx.x;
    const float* xp = x + (size_t)row * Dm;
    float s = 0.f, s2 = 0.f;
    for (int i = threadIdx.x; i < Dm; i += 256) { float v = xp[i]; s += v; s2 += v * v; }
    #pragma unroll
    for (int off = 16; off; off >>= 1) {
        s  += __shfl_xor_sync(0xffffffffu, s,  off);
        s2 += __shfl_xor_sync(0xffffffffu, s2, off);
    }
    __shared__ float rs[8], rs2[8];
    __shared__ float mean_s, inv_s;
    int w = threadIdx.x >> 5, l = threadIdx.x & 31;
    if (!l) { rs[w] = s; rs2[w] = s2; }
    __syncthreads();
    if (threadIdx.x == 0) {
        float a = 0.f, a2 = 0.f;
        #pragma unroll
        for (int i = 0; i < 8; i++) { a += rs[i]; a2 += rs2[i]; }
        float mean = a / Dm;
        float var  = a2 / Dm - mean * mean;
        mean_s = mean;
        inv_s  = rsqrtf(var + 1e-5f);
    }
    __syncthreads();
    float mean = mean_s, inv = inv_s;
    for (int i = threadIdx.x; i < Dm; i += 256) {
        float v = (xp[i] - mean) * inv;
        o1[(size_t)row * Dm + i] = v * w1[i] + b1[i];
        if (o2) o2[(size_t)row * Dm + i] = v * w2[i] + b2[i];
    }
}

// ---------------------------------------------------------------------------
// TF32 tensor-core GEMM, double-buffered. C = A[M,K] @ W[N,K]^T (+bias)(+act)(+resid)
// BM=128, BN=128, BK=16, 256 threads (8 warps, warp tile 64x32 of m16n8k8).
// ---------------------------------------------------------------------------
__device__ __forceinline__ unsigned f2tf(float x) {
    unsigned u;
    asm("cvt.rna.tf32.f32 %0, %1;" : "=r"(u) : "f"(x));
    return u;
}

__device__ __forceinline__ void mma_tf32(float* d, const unsigned* a, const unsigned* b) {
    asm volatile(
        "mma.sync.aligned.m16n8k8.row.col.f32.tf32.tf32.f32 "
        "{%0,%1,%2,%3}, {%4,%5,%6,%7}, {%8,%9}, {%0,%1,%2,%3};"
        : "+f"(d[0]), "+f"(d[1]), "+f"(d[2]), "+f"(d[3])
        : "r"(a[0]), "r"(a[1]), "r"(a[2]), "r"(a[3]), "r"(b[0]), "r"(b[1]));
}

#define LDT 20   // padded tile row length in words (16 + 4); 20 mod 32 = 4 -> conflict-free frags

__global__ void __launch_bounds__(256, 2) gemm_tf32_kernel(
    const float* __restrict__ A, int lda,
    const float* __restrict__ W, int ldw,
    int klen,
    const float* __restrict__ bias,
    const float* __restrict__ resid, int ldr,
    float* __restrict__ C, int ldc,
    int N, int act)
{
    __shared__ unsigned As[2][128][LDT];
    __shared__ unsigned Bs[2][128][LDT];

    const int tid  = threadIdx.x;
    const int lane = tid & 31;
    const int wid  = tid >> 5;
    const int m0   = (wid & 1) * 64;
    const int n0   = (wid >> 1) * 32;
    const int qr   = lane >> 2;
    const int qc   = lane & 3;

    const int bm = blockIdx.y * 128;
    const int bn = blockIdx.x * 128;
    const int ks = blockIdx.z * klen;

    // gmem staging mapping: two (row, ch) pairs per thread per matrix
    const int r0t = tid >> 2;          // 0..63
    const int r1t = r0t + 64;          // 64..127
    const int cht = (tid & 3) * 4;     // 0,4,8,12

    const float* Arow0 = A + (size_t)(bm + r0t) * lda + ks + cht;
    const float* Arow1 = A + (size_t)(bm + r1t) * lda + ks + cht;
    const bool  wok0 = (bn + r0t) < N;
    const bool  wok1 = (bn + r1t) < N;
    const float* Wrow0 = W + (size_t)(bn + r0t) * ldw + ks + cht;
    const float* Wrow1 = W + (size_t)(bn + r1t) * ldw + ks + cht;

    float acc[4][4][4];
    #pragma unroll
    for (int i = 0; i < 4; i++)
        #pragma unroll
        for (int j = 0; j < 4; j++)
            #pragma unroll
            for (int r = 0; r < 4; r++) acc[i][j][r] = 0.f;

    const int nk = klen >> 4;
    float4 a0, a1, b0, b1;

    // prologue: tile 0
    a0 = *(const float4*)Arow0;
    a1 = *(const float4*)Arow1;
    b0 = wok0 ? *(const float4*)Wrow0 : make_float4(0.f,0.f,0.f,0.f);
    b1 = wok1 ? *(const float4*)Wrow1 : make_float4(0.f,0.f,0.f,0.f);
    {
        unsigned* d0 = &As[0][r0t][cht]; d0[0]=f2tf(a0.x); d0[1]=f2tf(a0.y); d0[2]=f2tf(a0.z); d0[3]=f2tf(a0.w);
        unsigned* d1 = &As[0][r1t][cht]; d1[0]=f2tf(a1.x); d1[1]=f2tf(a1.y); d1[2]=f2tf(a1.z); d1[3]=f2tf(a1.w);
        unsigned* e0 = &Bs[0][r0t][cht]; e0[0]=f2tf(b0.x); e0[1]=f2tf(b0.y); e0[2]=f2tf(b0.z); e0[3]=f2tf(b0.w);
        unsigned* e1 = &Bs[0][r1t][cht]; e1[0]=f2tf(b1.x); e1[1]=f2tf(b1.y); e1[2]=f2tf(b1.z); e1[3]=f2tf(b1.w);
    }
    __syncthreads();

    for (int kt = 0; kt < nk; kt++) {
        const int cur = kt & 1;
        const bool hasnext = (kt + 1) < nk;
        if (hasnext) {
            const int off = (kt + 1) * 16;
            a0 = *(const float4*)(Arow0 + off);
            a1 = *(const float4*)(Arow1 + off);
            b0 = wok0 ? *(const float4*)(Wrow0 + off) : make_float4(0.f,0.f,0.f,0.f);
            b1 = wok1 ? *(const float4*)(Wrow1 + off) : make_float4(0.f,0.f,0.f,0.f);
        }
        #pragma unroll
        for (int kc = 0; kc < 16; kc += 8) {
            unsigned af[4][4], bf[4][2];
            #pragma unroll
            for (int mt = 0; mt < 4; mt++) {
                int r = m0 + mt * 16 + qr;
                af[mt][0] = As[cur][r][kc + qc];
                af[mt][1] = As[cur][r + 8][kc + qc];
                af[mt][2] = As[cur][r][kc + qc + 4];
                af[mt][3] = As[cur][r + 8][kc + qc + 4];
            }
            #pragma unroll
            for (int nt = 0; nt < 4; nt++) {
                int c = n0 + nt * 8 + qr;
                bf[nt][0] = Bs[cur][c][kc + qc];
                bf[nt][1] = Bs[cur][c][kc + qc + 4];
            }
            #pragma unroll
            for (int mt = 0; mt < 4; mt++)
                #pragma unroll
                for (int nt = 0; nt < 4; nt++)
                    mma_tf32(acc[mt][nt], af[mt], bf[nt]);
        }
        if (hasnext) {
            const int nxt = 1 - cur;
            unsigned* d0 = &As[nxt][r0t][cht]; d0[0]=f2tf(a0.x); d0[1]=f2tf(a0.y); d0[2]=f2tf(a0.z); d0[3]=f2tf(a0.w);
            unsigned* d1 = &As[nxt][r1t][cht]; d1[0]=f2tf(a1.x); d1[1]=f2tf(a1.y); d1[2]=f2tf(a1.z); d1[3]=f2tf(a1.w);
            unsigned* e0 = &Bs[nxt][r0t][cht]; e0[0]=f2tf(b0.x); e0[1]=f2tf(b0.y); e0[2]=f2tf(b0.z); e0[3]=f2tf(b0.w);
            unsigned* e1 = &Bs[nxt][r1t][cht]; e1[0]=f2tf(b1.x); e1[1]=f2tf(b1.y); e1[2]=f2tf(b1.z); e1[3]=f2tf(b1.w);
            __syncthreads();
        }
    }

    // epilogue
    #pragma unroll
    for (int mt = 0; mt < 4; mt++) {
        #pragma unroll
        for (int nt = 0; nt < 4; nt++) {
            int r = bm + m0 + mt * 16 + qr;
            int c = bn + n0 + nt * 8 + 2 * qc;
            #pragma unroll
            for (int half = 0; half < 2; half++) {
                int rr = r + half * 8;
                #pragma unroll
                for (int cc = 0; cc < 2; cc++) {
                    int gc = c + cc;
                    if (gc < N) {
                        float v = acc[mt][nt][half * 2 + cc];
                        if (bias)  v += bias[gc];
                        if (act)   v = (v > 20.f) ? v : log1pf(__expf(v));
                        if (resid) v += resid[(size_t)rr * ldr + gc];
                        C[(size_t)rr * ldc + gc] = v;
                    }
                }
            }
        }
    }
}

// reduce split-K partials for x_proj
__global__ void __launch_bounds__(256) reduce_xp_kernel(
    const float* __restrict__ part, float* __restrict__ out)
{
    int i = blockIdx.x * 256 + threadIdx.x;
    const int total = R_ROWS * 96;
    if (i < total) {
        float s = 0.f;
        #pragma unroll
        for (int z = 0; z < XP_SPLIT; z++) s += part[(size_t)z * total + i];
        out[i] = s;
    }
}

// ---------------------------------------------------------------------------
// Depthwise causal conv (width 4) along L + bias + SiLU.
// ---------------------------------------------------------------------------
__global__ void __launch_bounds__(256) conv_silu_kernel(
    const float* __restrict__ xr,
    const float* __restrict__ cw, const float* __restrict__ cb,
    float* __restrict__ u)
{
    int idx = blockIdx.x * 256 + threadIdx.x;
    int d = idx & (DIN - 1);
    int r = idx >> 11;
    int l = r & (LSEQ - 1);
    float acc = cb[d];
    const float* base = xr + (size_t)r * (2 * DIN) + d;
    #pragma unroll
    for (int k = 0; k < 4; k++) {
        int l2 = l - 3 + k;
        if (l2 >= 0) acc += cw[d * 4 + k] * base[(size_t)(l2 - l) * (2 * DIN)];
    }
    float sv = acc / (1.f + __expf(-acc));
    u[idx] = sv;
}

// ---------------------------------------------------------------------------
// Selective scan. 16 lanes per (b,d) chain (lane = state n).
// ---------------------------------------------------------------------------
__global__ void __launch_bounds__(256) scan_kernel(
    const float* __restrict__ delta, const float* __restrict__ u,
    const float* __restrict__ dbc,   const float* __restrict__ xr,
    const float* __restrict__ A_log, const float* __restrict__ Dskip,
    float* __restrict__ y)
{
    int t = blockIdx.x * 256 + threadIdx.x;
    int chain = t >> 4;
    int n = t & 15;
    int b = chain >> 11;
    int d = chain & (DIN - 1);
    float An = -__expf(A_log[d * DS + n]);
    float Dv = Dskip[d];
    float h = 0.f;
    size_t rowbase = (size_t)b * LSEQ;
    for (int l = 0; l < LSEQ; l++) {
        size_t row = rowbase + l;
        float dv = delta[row * DIN + d];
        float uv = u[row * DIN + d];
        float Bn = dbc[row * 96 + DTR + n];
        float Cn = dbc[row * 96 + DTR + DS + n];
        h = __expf(dv * An) * h + dv * Bn * uv;
        float p = h * Cn;
        p += __shfl_xor_sync(0xffffffffu, p, 8, 16);
        p += __shfl_xor_sync(0xffffffffu, p, 4, 16);
        p += __shfl_xor_sync(0xffffffffu, p, 2, 16);
        p += __shfl_xor_sync(0xffffffffu, p, 1, 16);
        if (n == 0) {
            float res = xr[row * (2 * DIN) + DIN + d];
            float sres = res / (1.f + __expf(-res));
            y[row * DIN + d] = (p + uv * Dv) * sres;
        }
    }
}

// ---------------------------------------------------------------------------
// Causal MQA attention. Thread per query, K/V tiles in smem, online softmax.
// ---------------------------------------------------------------------------
__global__ void __launch_bounds__(128) attn_kernel(
    const float* __restrict__ qkv, float* __restrict__ out)
{
    __shared__ float ks[64 * 64];
    __shared__ float vs[64 * 64];
    int b = blockIdx.z, h = blockIdx.y;
    int ql = blockIdx.x * 128 + threadIdx.x;
    size_t qrow = ((size_t)b * LSEQ + ql) * 1152;
    float4 q4[16];
    #pragma unroll
    for (int i = 0; i < 16; i++) q4[i] = *(const float4*)(qkv + qrow + h * HDIM + i * 4);
    float4 o4[16];
    #pragma unroll
    for (int i = 0; i < 16; i++) o4[i] = make_float4(0.f, 0.f, 0.f, 0.f);
    float m = -1e30f, lsum = 0.f;
    int ntiles = blockIdx.x * 2 + 2;
    for (int tk = 0; tk < ntiles; tk++) {
        int s0 = tk * 64;
        __syncthreads();
        for (int i = threadIdx.x; i < 64 * 16; i += 128) {
            int s = i >> 4, jj = i & 15;
            const float* kr = qkv + ((size_t)b * LSEQ + s0 + s) * 1152;
            ((float4*)ks)[i] = *(const float4*)(kr + 1024 + jj * 4);
            ((float4*)vs)[i] = *(const float4*)(kr + 1088 + jj * 4);
        }
        __syncthreads();
        int kcount = ql - s0 + 1;
        if (kcount > 64) kcount = 64;
        for (int s = 0; s < kcount; s++) {
            const float4* kp = (const float4*)(ks + s * 64);
            float sc = 0.f;
            #pragma unroll
            for (int i = 0; i < 16; i++) {
                float4 kk = kp[i];
                sc += q4[i].x * kk.x; sc += q4[i].y * kk.y;
                sc += q4[i].z * kk.z; sc += q4[i].w * kk.w;
            }
            sc *= 0.125f;
            const float4* vp = (const float4*)(vs + s * 64);
            if (sc <= m) {
                float p = __expf(sc - m);
                lsum += p;
                #pragma unroll
                for (int i = 0; i < 16; i++) {
                    float4 vv = vp[i];
                    o4[i].x += p * vv.x; o4[i].y += p * vv.y;
                    o4[i].z += p * vv.z; o4[i].w += p * vv.w;
                }
            } else {
                float sc2 = __expf(m - sc);
                m = sc;
                lsum = lsum * sc2 + 1.f;
                #pragma unroll
                for (int i = 0; i < 16; i++) {
                    float4 vv = vp[i];
                    o4[i].x = o4[i].x * sc2 + vv.x; o4[i].y = o4[i].y * sc2 + vv.y;
                    o4[i].z = o4[i].z * sc2 + vv.z; o4[i].w = o4[i].w * sc2 + vv.w;
                }
            }
        }
    }
    float inv = 1.f / lsum;
    float* op = out + ((size_t)b * LSEQ + ql) * D_MODEL + h * HDIM;
    #pragma unroll
    for (int i = 0; i < 16; i++) {
        float4 vv;
        vv.x = o4[i].x * inv; vv.y = o4[i].y * inv;
        vv.z = o4[i].z * inv; vv.w = o4[i].w * inv;
        *(float4*)(op + i * 4) = vv;
    }
}

// ---------------------------------------------------------------------------
// Launch
// ---------------------------------------------------------------------------
extern "C" void kernel_launch(void* const* d_in, const int* in_sizes, int n_in,
                              void* d_out, int out_size)
{
    const float* x          = (const float*)d_in[0];
    const float* mnorm_w    = (const float*)d_in[1];
    const float* mnorm_b    = (const float*)d_in[2];
    const float* in_proj_w  = (const float*)d_in[3];
    const float* conv_w     = (const float*)d_in[4];
    const float* conv_b     = (const float*)d_in[5];
    const float* x_proj_w   = (const float*)d_in[6];
    const float* dt_proj_w  = (const float*)d_in[7];
    const float* dt_proj_b  = (const float*)d_in[8];
    const float* A_log      = (const float*)d_in[9];
    const float* D_skip     = (const float*)d_in[10];
    const float* out_proj_w = (const float*)d_in[11];
    const float* norm1_w    = (const float*)d_in[12];
    const float* norm1_b    = (const float*)d_in[13];
    const float* wqkv_w     = (const float*)d_in[14];
    const float* wqkv_b     = (const float*)d_in[15];
    const float* oattn_w    = (const float*)d_in[16];
    const float* oattn_b    = (const float*)d_in[17];
    const float* fuse_w     = (const float*)d_in[18];
    const float* fuse_b     = (const float*)d_in[19];
    const float* fln_w      = (const float*)d_in[20];
    const float* fln_b      = (const float*)d_in[21];
    float* out = (float*)d_out;

    float *xnm, *xna, *xr, *u, *dbc, *xpart, *delta, *y, *qkv, *ao, *comb, *fpre;
    cudaGetSymbolAddress((void**)&xnm,   g_xnm);
    cudaGetSymbolAddress((void**)&xna,   g_xna);
    cudaGetSymbolAddress((void**)&xr,    g_xr);
    cudaGetSymbolAddress((void**)&u,     g_u);
    cudaGetSymbolAddress((void**)&dbc,   g_dbc);
    cudaGetSymbolAddress((void**)&xpart, g_xpart);
    cudaGetSymbolAddress((void**)&delta, g_delta);
    cudaGetSymbolAddress((void**)&y,     g_y);
    cudaGetSymbolAddress((void**)&qkv,   g_qkv);
    cudaGetSymbolAddress((void**)&ao,    g_ao);
    cudaGetSymbolAddress((void**)&comb,  g_comb);
    cudaGetSymbolAddress((void**)&fpre,  g_fpre);

    // 1. Both input LayerNorms (shared stats)
    ln_dual_kernel<<<R_ROWS, 256>>>(x, mnorm_w, mnorm_b, xnm, norm1_w, norm1_b, xna);

    // 2. in_proj: xr = xnm @ in_proj_w^T   (2048 x 4096, K=1024)
    gemm_tf32_kernel<<<dim3(4096 / 128, R_ROWS / 128, 1), 256>>>(
        xnm, D_MODEL, in_proj_w, D_MODEL, D_MODEL,
        nullptr, nullptr, 0, xr, 2 * DIN, 2 * DIN, 0);

    // 3. depthwise conv + SiLU -> u
    conv_silu_kernel<<<(R_ROWS * DIN) / 256, 256>>>(xr, conv_w, conv_b, u);

    // 4. x_proj split-K: partials (2048 x 96, K=2048, 8 slices of 256)
    gemm_tf32_kernel<<<dim3(1, R_ROWS / 128, XP_SPLIT), 256>>>(
        u, DIN, x_proj_w, DIN, DIN / XP_SPLIT,
        nullptr, nullptr, 0, xpart, 96, 96, 0);
    reduce_xp_kernel<<<(R_ROWS * 96 + 255) / 256, 256>>>(xpart, dbc);

    // 5. dt_proj + softplus: delta (2048 x 2048, K=64, lda=96)
    gemm_tf32_kernel<<<dim3(DIN / 128, R_ROWS / 128, 1), 256>>>(
        dbc, 96, dt_proj_w, DTR, DTR,
        dt_proj_b, nullptr, 0, delta, DIN, DIN, 1);

    // 6. selective scan (+ D_skip + silu(res) gate)
    scan_kernel<<<(BATCH * DIN * 16) / 256, 256>>>(delta, u, dbc, xr, A_log, D_skip, y);

    // 7. out_proj + residual x -> comb[:, :1024]
    gemm_tf32_kernel<<<dim3(D_MODEL / 128, R_ROWS / 128, 1), 256>>>(
        y, DIN, out_proj_w, DIN, DIN,
        nullptr, x, D_MODEL, comb, 2 * D_MODEL, D_MODEL, 0);

    // 8. wqkv (+bias): qkv (2048 x 1152, K=1024)
    gemm_tf32_kernel<<<dim3(1152 / 128, R_ROWS / 128, 1), 256>>>(
        xna, D_MODEL, wqkv_w, D_MODEL, D_MODEL,
        wqkv_b, nullptr, 0, qkv, 1152, 1152, 0);

    // 9. causal MQA attention -> ao
    attn_kernel<<<dim3(LSEQ / 128, NHEAD, BATCH), 128>>>(qkv, ao);

    // 10. oattn (+bias) + residual x -> comb[:, 1024:]
    gemm_tf32_kernel<<<dim3(D_MODEL / 128, R_ROWS / 128, 1), 256>>>(
        ao, D_MODEL, oattn_w, D_MODEL, D_MODEL,
        oattn_b, x, D_MODEL, comb + D_MODEL, 2 * D_MODEL, D_MODEL, 0);

    // 11. fuse GEMM (+bias): fpre = comb @ fuse_w^T  (2048 x 1024, K=2048)
    gemm_tf32_kernel<<<dim3(D_MODEL / 128, R_ROWS / 128, 1), 256>>>(
        comb, 2 * D_MODEL, fuse_w, 2 * D_MODEL, 2 * D_MODEL,
        fuse_b, nullptr, 0, fpre, D_MODEL, D_MODEL, 0);

    // 12. final LayerNorm -> out
    ln_dual_kernel<<<R_ROWS, 256>>>(fpre, fln_w, fln_b, out, nullptr, nullptr, nullptr);
}